// round 9
// baseline (speedup 1.0000x reference)
#include <cuda_runtime.h>
#include <cuda_bf16.h>
#include <cstdint>
#include <math.h>

#define NUM_TOKENS 16384
#define NUM_EXPERTS 256
#define HIDDEN     7168
#define M_TILE     128
#define KC         64
#define NCHUNKS    (HIDDEN / KC)          // 112
#define NTH        256

// Margin thresholds (score-space). 3-product GEMM score error ~1e-5 (5 sigma).
#define TAU_E 1e-4f
#define TAU_G 2e-4f

// Row stride in the bf16 tiles: 64 halves data + 8 halves pad = 144 bytes.
#define RSTRIDE      144
#define A_TILE_B     (M_TILE * RSTRIDE)        // 18432
#define W_TILE_B     (NUM_EXPERTS * RSTRIDE)   // 36864
#define OFF_AHI      0
#define OFF_ALO      A_TILE_B
#define OFF_WHI      (2 * A_TILE_B)
#define OFF_WLO      (OFF_WHI + W_TILE_B)
#define STAGE_B      (OFF_WLO + W_TILE_B)      // 110592
#define SMEM_TOTAL   (2 * STAGE_B)             // 221184

#define LSTRIDE_B    1056                      // 264 floats per logits row

typedef unsigned long long ull;

// W pre-converted to bf16 hi/lo, [NCHUNKS][256 rows][144 B] — same layout as smem.
__device__ uint8_t g_Whi[NCHUNKS * W_TILE_B];
__device__ uint8_t g_Wlo[NCHUNKS * W_TILE_B];

// Margin-triggered repair list
__device__ int g_fix_cnt;
__device__ int g_fix_list[NUM_TOKENS];

// ---------------- helpers ---------------------------------------------------
__device__ __forceinline__ uint32_t smem_u32(const void* p) {
    uint32_t a;
    asm("{ .reg .u64 t; cvta.to.shared.u64 t, %1; cvt.u32.u64 %0, t; }" : "=r"(a) : "l"(p));
    return a;
}
#define CP_ASYNC16(dst, src) \
    asm volatile("cp.async.cg.shared.global [%0], [%1], 16;" :: "r"((uint32_t)(dst)), "l"(src))
#define CP_COMMIT() asm volatile("cp.async.commit_group;" ::: "memory")
#define CP_WAIT0()  asm volatile("cp.async.wait_group 0;" ::: "memory")

__device__ __forceinline__ void sts8(uint32_t a, uint32_t x, uint32_t y) {
    asm volatile("st.shared.v2.b32 [%0], {%1, %2};" :: "r"(a), "r"(x), "r"(y));
}
__device__ __forceinline__ float4 lds16f(uint32_t a) {
    float4 v;
    asm volatile("ld.shared.v4.f32 {%0, %1, %2, %3}, [%4];"
                 : "=f"(v.x), "=f"(v.y), "=f"(v.z), "=f"(v.w) : "r"(a));
    return v;
}
__device__ __forceinline__ uint32_t packbf(__nv_bfloat16 a, __nv_bfloat16 b) {
    __nv_bfloat162 t; t.x = a; t.y = b;
    return *reinterpret_cast<uint32_t*>(&t);
}
__device__ __forceinline__ void ldm_x4(uint32_t* r, uint32_t addr) {
    asm volatile("ldmatrix.sync.aligned.m8n8.x4.shared.b16 {%0,%1,%2,%3}, [%4];"
                 : "=r"(r[0]), "=r"(r[1]), "=r"(r[2]), "=r"(r[3]) : "r"(addr));
}
__device__ __forceinline__ void mma16816(float* d, const uint32_t* a, const uint32_t* b) {
    asm volatile(
        "mma.sync.aligned.m16n8k16.row.col.f32.bf16.bf16.f32 "
        "{%0,%1,%2,%3}, {%4,%5,%6,%7}, {%8,%9}, {%0,%1,%2,%3};"
        : "+f"(d[0]), "+f"(d[1]), "+f"(d[2]), "+f"(d[3])
        : "r"(a[0]), "r"(a[1]), "r"(a[2]), "r"(a[3]), "r"(b[0]), "r"(b[1]));
}
__device__ __forceinline__ void fma2(ull& acc, ull a, ull b) {
    asm("fma.rn.f32x2 %0, %1, %2, %0;" : "+l"(acc) : "l"(a), "l"(b));
}
__device__ __forceinline__ ull pack2(float x, float y) {
    ull r; asm("mov.b64 %0, {%1, %2};" : "=l"(r) : "f"(x), "f"(y)); return r;
}
__device__ __forceinline__ float2 unpack2(ull v) {
    float2 f; asm("mov.b64 {%0, %1}, %2;" : "=f"(f.x), "=f"(f.y) : "l"(v)); return f;
}

// ---------------------------------------------------------------------------
// Kernel 0: W fp32 -> bf16 hi/lo, chunk-tiled, stride-144 (== smem layout)
// Also zeroes the repair counter each launch.
// ---------------------------------------------------------------------------
__global__ __launch_bounds__(256)
void convert_w_kernel(const float* __restrict__ W) {
    if (blockIdx.x == 0 && threadIdx.x == 0) g_fix_cnt = 0;

    const int K4 = HIDDEN / 4;                          // 1792
    size_t tix = (size_t)blockIdx.x * 256 + threadIdx.x;
    int n = (int)(tix / K4);
    int k = (int)(tix % K4) * 4;
    float4 v = *reinterpret_cast<const float4*>(W + (size_t)n * HIDDEN + k);

    __nv_bfloat16 hx = __float2bfloat16_rn(v.x);
    __nv_bfloat16 hy = __float2bfloat16_rn(v.y);
    __nv_bfloat16 hz = __float2bfloat16_rn(v.z);
    __nv_bfloat16 hw = __float2bfloat16_rn(v.w);
    __nv_bfloat16 lx = __float2bfloat16_rn(v.x - __bfloat162float(hx));
    __nv_bfloat16 ly = __float2bfloat16_rn(v.y - __bfloat162float(hy));
    __nv_bfloat16 lz = __float2bfloat16_rn(v.z - __bfloat162float(hz));
    __nv_bfloat16 lw = __float2bfloat16_rn(v.w - __bfloat162float(hw));

    int chunk = k >> 6;
    int kc    = k & 63;
    size_t base = (size_t)chunk * W_TILE_B + (size_t)n * RSTRIDE + kc * 2;
    *reinterpret_cast<uint2*>(g_Whi + base) = make_uint2(packbf(hx, hy), packbf(hz, hw));
    *reinterpret_cast<uint2*>(g_Wlo + base) = make_uint2(packbf(lx, ly), packbf(lz, lw));
}

// ---------------------------------------------------------------------------
// Routing (round-1 verified math) + decision margins. One warp = 1 token.
// ---------------------------------------------------------------------------
__device__ __forceinline__ void route_token(const float lg[8], const float bs[8],
                                            float* __restrict__ orow, int lane,
                                            float& margin_g, float& margin_e) {
    float score[8], swb[8];
#pragma unroll
    for (int i = 0; i < 8; i++) {
        float x = lg[i];
        float s;
        if (x >= 0.0f) { float z = expf(-x); s = 1.0f / (1.0f + z); }
        else           { float z = expf(x);  s = z / (1.0f + z); }
        score[i] = s;
        swb[i]   = s + bs[i];
    }

    float h1 = -INFINITY, h2 = -INFINITY;
#pragma unroll
    for (int i = 0; i < 8; i++) {
        float v = swb[i];
        if (v > h1) { h2 = h1; h1 = v; }
        else if (v > h2) { h2 = v; }
    }
#pragma unroll
    for (int m = 1; m <= 2; m <<= 1) {
        float o1 = __shfl_xor_sync(0xffffffffu, h1, m);
        float o2 = __shfl_xor_sync(0xffffffffu, h2, m);
        float a = fmaxf(h1, o1);
        float b = fminf(h1, o1);
        float c = fmaxf(fmaxf(h2, o2), b);
        h1 = a; h2 = c;
    }
    float gscore = h1 + h2;

    float gs[8];
#pragma unroll
    for (int g = 0; g < 8; g++) gs[g] = __shfl_sync(0xffffffffu, gscore, g * 4);

    unsigned gmask = 0;
    float val4 = 0.0f, val5 = 0.0f;
#pragma unroll
    for (int r = 0; r < 5; r++) {
        float best = -INFINITY; int bi = 0;
#pragma unroll
        for (int g = 0; g < 8; g++) {
            bool avail = !((gmask >> g) & 1u);
            if (avail && gs[g] > best) { best = gs[g]; bi = g; }
        }
        if (r < 4) { gmask |= 1u << bi; val4 = best; }
        else       { val5 = best; }
    }
    margin_g = val4 - val5;

    const bool inmask = (gmask >> (lane >> 2)) & 1u;
    const int ebase = lane * 8;
    float mval[8];
#pragma unroll
    for (int i = 0; i < 8; i++) mval[i] = inmask ? swb[i] : 0.0f;

    unsigned selbits = 0;
    float v8 = 0.0f, v9 = 0.0f;
#pragma unroll
    for (int r = 0; r < 9; r++) {
        float bv = -INFINITY; int bidx = 0x3fffffff;
#pragma unroll
        for (int i = 0; i < 8; i++) {
            if (!((selbits >> i) & 1u)) {
                float v = mval[i]; int e = ebase + i;
                if (v > bv || (v == bv && e < bidx)) { bv = v; bidx = e; }
            }
        }
#pragma unroll
        for (int off = 16; off >= 1; off >>= 1) {
            float ov = __shfl_xor_sync(0xffffffffu, bv, off);
            int   oi = __shfl_xor_sync(0xffffffffu, bidx, off);
            if (ov > bv || (ov == bv && oi < bidx)) { bv = ov; bidx = oi; }
        }
        if (r < 8) {
            if ((bidx >> 3) == lane) selbits |= 1u << (bidx & 7);
            if (r == 7) v8 = bv;
        } else v9 = bv;
    }
    margin_e = v8 - v9;

    float d = 0.0f;
#pragma unroll
    for (int i = 0; i < 8; i++) if ((selbits >> i) & 1u) d += score[i];
#pragma unroll
    for (int off = 16; off >= 1; off >>= 1) d += __shfl_xor_sync(0xffffffffu, d, off);
    d += 1e-20f;

    float o[8];
#pragma unroll
    for (int i = 0; i < 8; i++)
        o[i] = ((selbits >> i) & 1u) ? (score[i] / d) * 2.5f : 0.0f;

    *reinterpret_cast<float4*>(&orow[ebase])     = make_float4(o[0], o[1], o[2], o[3]);
    *reinterpret_cast<float4*>(&orow[ebase + 4]) = make_float4(o[4], o[5], o[6], o[7]);
}

// ---------------------------------------------------------------------------
// Kernel 1: fused gate GEMM (3-product split bf16 mma.sync) + routing + triggers
// Pipelined fragments (af/bf double buffer); A LDG/STS after compute so the
// accumulator region carries no long-lived A registers.
// ---------------------------------------------------------------------------
__global__ __launch_bounds__(NTH, 1)
void gate_fused_kernel(const float* __restrict__ A, const float* __restrict__ bias,
                       float* __restrict__ out) {
    extern __shared__ char smem[];
    const uint32_t sb = smem_u32(smem);
    const int tid  = threadIdx.x;
    const int lane = tid & 31;
    const int w    = tid >> 5;
    const int wm   = w >> 2;
    const int wn   = w & 3;
    const int m0   = blockIdx.x * M_TILE;

    float4 bv0 = *reinterpret_cast<const float4*>(bias + lane * 8);
    float4 bv1 = *reinterpret_cast<const float4*>(bias + lane * 8 + 4);

    const int arow = tid >> 1;
    const int ahalf = tid & 1;
    const float* abase_g = A + (size_t)(m0 + arow) * HIDDEN + ahalf * 32;
    const uint32_t asts_base = (uint32_t)(arow * RSTRIDE + ahalf * 64);

    // LDA+STA fused: registers live only inside this call
    auto LDSTA = [&](int it, uint32_t buf) {
        const float4* p = reinterpret_cast<const float4*>(abase_g + it * KC);
        float4 areg[8];
#pragma unroll
        for (int j = 0; j < 8; j++) areg[j] = p[j];
        const uint32_t hb = buf + OFF_AHI + asts_base;
        const uint32_t lb = buf + OFF_ALO + asts_base;
#pragma unroll
        for (int j = 0; j < 8; j++) {
            float4 v = areg[j];
            __nv_bfloat16 hx = __float2bfloat16_rn(v.x);
            __nv_bfloat16 hy = __float2bfloat16_rn(v.y);
            __nv_bfloat16 hz = __float2bfloat16_rn(v.z);
            __nv_bfloat16 hw = __float2bfloat16_rn(v.w);
            sts8(hb + 8 * j, packbf(hx, hy), packbf(hz, hw));
            __nv_bfloat16 lx = __float2bfloat16_rn(v.x - __bfloat162float(hx));
            __nv_bfloat16 ly = __float2bfloat16_rn(v.y - __bfloat162float(hy));
            __nv_bfloat16 lz = __float2bfloat16_rn(v.z - __bfloat162float(hz));
            __nv_bfloat16 lw = __float2bfloat16_rn(v.w - __bfloat162float(hw));
            sts8(lb + 8 * j, packbf(lx, ly), packbf(lz, lw));
        }
    };
    auto CPW = [&](int it, uint32_t buf) {
        const uint8_t* wh = g_Whi + (size_t)it * W_TILE_B;
        const uint8_t* wl = g_Wlo + (size_t)it * W_TILE_B;
#pragma unroll
        for (int i = 0; i < 9; i++) {
            uint32_t off = (uint32_t)(i * 256 + tid) * 16;
            CP_ASYNC16(buf + OFF_WHI + off, wh + off);
            CP_ASYNC16(buf + OFF_WLO + off, wl + off);
        }
    };

    const uint32_t a_lane = (uint32_t)((lane & 15) * RSTRIDE + (lane >> 4) * 16);
    const uint32_t b_lane = (uint32_t)(((lane & 7) + ((lane >> 4) & 1) * 8) * RSTRIDE
                                       + ((lane >> 3) & 1) * 16);
    const uint32_t am_base = (uint32_t)(wm * 64 * RSTRIDE);
    const uint32_t bn_base = (uint32_t)(wn * 64 * RSTRIDE);

    // Fragment double buffers (pipeline depth 2)
    uint32_t af[2][16], bf[2][16];
    // combo c (0..11): ks = c>>2? No — ks = c/3, p = c%3 (ks-major, p minor)
    auto LDFRAG = [&](int slot, uint32_t cur, int ks, int p) {
        const uint32_t kb = (uint32_t)ks * 32;
        const uint32_t ab = cur + (p == 2 ? OFF_ALO : OFF_AHI) + am_base + kb + a_lane;
        const uint32_t bb = cur + (p == 1 ? OFF_WLO : OFF_WHI) + bn_base + kb + b_lane;
#pragma unroll
        for (int mi = 0; mi < 4; mi++) ldm_x4(af[slot] + mi * 4, ab + mi * 16 * RSTRIDE);
#pragma unroll
        for (int q = 0; q < 4; q++)    ldm_x4(bf[slot] + q  * 4, bb + q  * 16 * RSTRIDE);
    };

    float acc[4][8][4];
#pragma unroll
    for (int mi = 0; mi < 4; mi++)
#pragma unroll
        for (int ni = 0; ni < 8; ni++)
#pragma unroll
            for (int q = 0; q < 4; q++) acc[mi][ni][q] = 0.0f;

    // ---- prologue
    {
        CPW(0, sb); CP_COMMIT();
        LDSTA(0, sb);
        CP_WAIT0();
        __syncthreads();
        LDFRAG(0, sb, 0, 0);          // combo 0 of iteration 0
    }

    for (int it = 0; it < NCHUNKS; it++) {
        const uint32_t cur = sb + (uint32_t)(it & 1) * STAGE_B;
        const uint32_t nxt = sb + (uint32_t)((it + 1) & 1) * STAGE_B;
        const bool more = (it + 1 < NCHUNKS);

        if (more) { CPW(it + 1, nxt); CP_COMMIT(); }

        // 12 combos, fragment loads pipelined one combo ahead
#pragma unroll
        for (int c = 0; c < 12; c++) {
            if (c < 11) LDFRAG((c + 1) & 1, cur, (c + 1) / 3, (c + 1) % 3);
            const uint32_t* a_ = af[c & 1];
            const uint32_t* b_ = bf[c & 1];
#pragma unroll
            for (int mi = 0; mi < 4; mi++)
#pragma unroll
                for (int ni = 0; ni < 8; ni++)
                    mma16816(acc[mi][ni], a_ + mi * 4, b_ + (ni >> 1) * 4 + (ni & 1) * 2);
        }

        if (more) LDSTA(it + 1, nxt);   // nxt A-planes free since end of it-1
        CP_WAIT0();
        __syncthreads();
        if (more) LDFRAG(0, nxt, 0, 0); // seam: combo 0 of next iteration
    }

    // ---- epilogue: accum frags -> smem logits
    {
        const int gid = lane >> 2;
        const int tig = lane & 3;
#pragma unroll
        for (int mi = 0; mi < 4; mi++) {
#pragma unroll
            for (int ni = 0; ni < 8; ni++) {
                const int col = wn * 64 + ni * 8 + tig * 2;
                const int r0 = wm * 64 + mi * 16 + gid;
                uint32_t a0 = sb + (uint32_t)r0 * LSTRIDE_B + col * 4;
                sts8(a0, __float_as_uint(acc[mi][ni][0]), __float_as_uint(acc[mi][ni][1]));
                sts8(a0 + 8u * LSTRIDE_B, __float_as_uint(acc[mi][ni][2]),
                                          __float_as_uint(acc[mi][ni][3]));
            }
        }
    }
    __syncthreads();

    // ---- fused routing + margin triggers
    {
        const float bs[8] = {bv0.x, bv0.y, bv0.z, bv0.w, bv1.x, bv1.y, bv1.z, bv1.w};
        for (int i = 0; i < 16; i++) {
            const int t = w * 16 + i;
            const uint32_t src = sb + (uint32_t)t * LSTRIDE_B + lane * 32;
            float4 l0 = lds16f(src);
            float4 l1 = lds16f(src + 16);
            const float lg[8] = {l0.x, l0.y, l0.z, l0.w, l1.x, l1.y, l1.z, l1.w};
            float mg, me;
            route_token(lg, bs, out + (size_t)(m0 + t) * NUM_EXPERTS, lane, mg, me);
            if (lane == 0 && (mg < TAU_G || me < TAU_E)) {
                int p = atomicAdd(&g_fix_cnt, 1);
                if (p < NUM_TOKENS) g_fix_list[p] = m0 + t;
            }
        }
    }
}

// ---------------------------------------------------------------------------
// Kernel 2: exact fp32 repair of marginal tokens. 4 tokens per block-chunk.
// ---------------------------------------------------------------------------
__global__ __launch_bounds__(256)
void repair_kernel(const float* __restrict__ A, const float* __restrict__ W,
                   const float* __restrict__ bias, float* __restrict__ out) {
    __shared__ float sA[4][1024];
    __shared__ float sLog[4][264];

    const int tid  = threadIdx.x;
    const int lane = tid & 31;
    const int w    = tid >> 5;
    const int cnt  = g_fix_cnt;

    float4 bv0 = *reinterpret_cast<const float4*>(bias + lane * 8);
    float4 bv1 = *reinterpret_cast<const float4*>(bias + lane * 8 + 4);
    const float bs[8] = {bv0.x, bv0.y, bv0.z, bv0.w, bv1.x, bv1.y, bv1.z, bv1.w};

    const float* wrow = W + (size_t)tid * HIDDEN;

    for (int base = blockIdx.x * 4; base < cnt; base += gridDim.x * 4) {
        int tk[4];
#pragma unroll
        for (int i = 0; i < 4; i++) {
            int idx = base + i;
            tk[i] = g_fix_list[idx < cnt ? idx : cnt - 1];
        }

        ull acc[4][2];
#pragma unroll
        for (int t = 0; t < 4; t++) { acc[t][0] = 0ull; acc[t][1] = 0ull; }

        for (int kt = 0; kt < 7; kt++) {
            __syncthreads();
#pragma unroll
            for (int j = 0; j < 4; j++) {
                int idx = j * 256 + tid;
                int t  = idx >> 8;
                int k4 = (idx & 255) * 4;
                *reinterpret_cast<float4*>(&sA[t][k4]) =
                    *reinterpret_cast<const float4*>(A + (size_t)tk[t] * HIDDEN + kt * 1024 + k4);
            }
            __syncthreads();

            const float4* wp = reinterpret_cast<const float4*>(wrow + kt * 1024);
#pragma unroll 4
            for (int k4 = 0; k4 < 256; k4++) {
                float4 wv = wp[k4];
                ull wxy = pack2(wv.x, wv.y);
                ull wzw = pack2(wv.z, wv.w);
#pragma unroll
                for (int t = 0; t < 4; t++) {
                    const ull* av = reinterpret_cast<const ull*>(&sA[t][k4 * 4]);
                    fma2(acc[t][0], av[0], wxy);
                    fma2(acc[t][1], av[1], wzw);
                }
            }
        }

#pragma unroll
        for (int t = 0; t < 4; t++) {
            float2 u0 = unpack2(acc[t][0]);
            float2 u1 = unpack2(acc[t][1]);
            sLog[t][tid] = (u0.x + u1.x) + (u0.y + u1.y);
        }
        __syncthreads();

        if (w < 4) {
            float4 l0 = *reinterpret_cast<const float4*>(&sLog[w][lane * 8]);
            float4 l1 = *reinterpret_cast<const float4*>(&sLog[w][lane * 8 + 4]);
            const float lg[8] = {l0.x, l0.y, l0.z, l0.w, l1.x, l1.y, l1.z, l1.w};
            float mg, me;
            route_token(lg, bs, out + (size_t)tk[w] * NUM_EXPERTS, lane, mg, me);
        }
        __syncthreads();
    }
}

// ---------------------------------------------------------------------------
extern "C" void kernel_launch(void* const* d_in, const int* in_sizes, int n_in,
                              void* d_out, int out_size) {
    const float* hidden = (const float*)d_in[0];   // [16384, 7168]
    const float* weight = (const float*)d_in[1];   // [256, 7168]
    const float* bias   = (const float*)d_in[2];   // [256]
    float* out = (float*)d_out;                    // [16384, 256]

    convert_w_kernel<<<(NUM_EXPERTS * HIDDEN / 4) / 256, 256>>>(weight);

    cudaFuncSetAttribute(gate_fused_kernel,
                         cudaFuncAttributeMaxDynamicSharedMemorySize, SMEM_TOTAL);
    gate_fused_kernel<<<NUM_TOKENS / M_TILE, NTH, SMEM_TOTAL>>>(hidden, bias, out);

    repair_kernel<<<128, 256>>>(hidden, weight, bias, out);
}

// round 10
// speedup vs baseline: 1.0040x; 1.0040x over previous
#include <cuda_runtime.h>
#include <cuda_bf16.h>
#include <cuda_fp16.h>
#include <cstdint>
#include <math.h>

#define NUM_TOKENS 16384
#define NUM_EXPERTS 256
#define HIDDEN     7168
#define M_TILE     128
#define KC         64
#define NCHUNKS    (HIDDEN / KC)          // 112
#define NTH        256

// Margin thresholds (score-space). fp16 single-product score error ~5e-5 (1 sigma).
#define TAU_E 6e-4f
#define TAU_G 1e-3f

// Row stride in the fp16 tiles: 64 halves data (128 B) + 16 B pad = 144 bytes.
#define RSTRIDE      144
#define A_TILE_B     (M_TILE * RSTRIDE)        // 18432
#define W_TILE_B     (NUM_EXPERTS * RSTRIDE)   // 36864
#define OFF_A        0
#define OFF_W        A_TILE_B                  // 18432
#define STAGE_B      (OFF_W + W_TILE_B)        // 55296
#define LSTRIDE_B    1056                      // 264 floats per logits row
#define SMEM_TOTAL   (M_TILE * LSTRIDE_B)      // 135168 (> 2*STAGE_B = 110592)

typedef unsigned long long ull;

// W pre-converted to fp16, chunk-tiled [NCHUNKS][256 rows][144 B] == smem layout.
__device__ uint8_t g_Wh[NCHUNKS * W_TILE_B];

// Margin-triggered repair list
__device__ int g_fix_cnt;
__device__ int g_fix_list[NUM_TOKENS];

// ---------------- helpers ---------------------------------------------------
__device__ __forceinline__ uint32_t smem_u32(const void* p) {
    uint32_t a;
    asm("{ .reg .u64 t; cvta.to.shared.u64 t, %1; cvt.u32.u64 %0, t; }" : "=r"(a) : "l"(p));
    return a;
}
#define CP_ASYNC16(dst, src) \
    asm volatile("cp.async.cg.shared.global [%0], [%1], 16;" :: "r"((uint32_t)(dst)), "l"(src))
#define CP_COMMIT() asm volatile("cp.async.commit_group;" ::: "memory")
#define CP_WAIT0()  asm volatile("cp.async.wait_group 0;" ::: "memory")

__device__ __forceinline__ void sts8(uint32_t a, uint32_t x, uint32_t y) {
    asm volatile("st.shared.v2.b32 [%0], {%1, %2};" :: "r"(a), "r"(x), "r"(y));
}
__device__ __forceinline__ float4 lds16f(uint32_t a) {
    float4 v;
    asm volatile("ld.shared.v4.f32 {%0, %1, %2, %3}, [%4];"
                 : "=f"(v.x), "=f"(v.y), "=f"(v.z), "=f"(v.w) : "r"(a));
    return v;
}
__device__ __forceinline__ uint32_t packh(__half a, __half b) {
    __half2 t; t.x = a; t.y = b;
    return *reinterpret_cast<uint32_t*>(&t);
}
__device__ __forceinline__ void ldm_x4(uint32_t* r, uint32_t addr) {
    asm volatile("ldmatrix.sync.aligned.m8n8.x4.shared.b16 {%0,%1,%2,%3}, [%4];"
                 : "=r"(r[0]), "=r"(r[1]), "=r"(r[2]), "=r"(r[3]) : "r"(addr));
}
__device__ __forceinline__ void mma16816(float* d, const uint32_t* a, const uint32_t* b) {
    asm volatile(
        "mma.sync.aligned.m16n8k16.row.col.f32.f16.f16.f32 "
        "{%0,%1,%2,%3}, {%4,%5,%6,%7}, {%8,%9}, {%0,%1,%2,%3};"
        : "+f"(d[0]), "+f"(d[1]), "+f"(d[2]), "+f"(d[3])
        : "r"(a[0]), "r"(a[1]), "r"(a[2]), "r"(a[3]), "r"(b[0]), "r"(b[1]));
}
__device__ __forceinline__ void fma2(ull& acc, ull a, ull b) {
    asm("fma.rn.f32x2 %0, %1, %2, %0;" : "+l"(acc) : "l"(a), "l"(b));
}
__device__ __forceinline__ ull pack2(float x, float y) {
    ull r; asm("mov.b64 %0, {%1, %2};" : "=l"(r) : "f"(x), "f"(y)); return r;
}
__device__ __forceinline__ float2 unpack2(ull v) {
    float2 f; asm("mov.b64 {%0, %1}, %2;" : "=f"(f.x), "=f"(f.y) : "l"(v)); return f;
}

// ---------------------------------------------------------------------------
// Kernel 0: W fp32 -> fp16, chunk-tiled, stride-144 (== smem layout).
// Also zeroes the repair counter each launch (graph-replay safe).
// ---------------------------------------------------------------------------
__global__ __launch_bounds__(256)
void convert_w_kernel(const float* __restrict__ W) {
    if (blockIdx.x == 0 && threadIdx.x == 0) g_fix_cnt = 0;

    const int K4 = HIDDEN / 4;                          // 1792
    size_t tix = (size_t)blockIdx.x * 256 + threadIdx.x;
    int n = (int)(tix / K4);
    int k = (int)(tix % K4) * 4;
    float4 v = *reinterpret_cast<const float4*>(W + (size_t)n * HIDDEN + k);

    uint32_t p0 = packh(__float2half_rn(v.x), __float2half_rn(v.y));
    uint32_t p1 = packh(__float2half_rn(v.z), __float2half_rn(v.w));

    int chunk = k >> 6;
    int kc    = k & 63;
    size_t base = (size_t)chunk * W_TILE_B + (size_t)n * RSTRIDE + kc * 2;
    *reinterpret_cast<uint2*>(g_Wh + base) = make_uint2(p0, p1);
}

// ---------------------------------------------------------------------------
// Routing (round-1 verified math) + decision margins. One warp = 1 token.
// ---------------------------------------------------------------------------
__device__ __forceinline__ void route_token(const float lg[8], const float bs[8],
                                            float* __restrict__ orow, int lane,
                                            float& margin_g, float& margin_e) {
    float score[8], swb[8];
#pragma unroll
    for (int i = 0; i < 8; i++) {
        float x = lg[i];
        float s;
        if (x >= 0.0f) { float z = expf(-x); s = 1.0f / (1.0f + z); }
        else           { float z = expf(x);  s = z / (1.0f + z); }
        score[i] = s;
        swb[i]   = s + bs[i];
    }

    float h1 = -INFINITY, h2 = -INFINITY;
#pragma unroll
    for (int i = 0; i < 8; i++) {
        float v = swb[i];
        if (v > h1) { h2 = h1; h1 = v; }
        else if (v > h2) { h2 = v; }
    }
#pragma unroll
    for (int m = 1; m <= 2; m <<= 1) {
        float o1 = __shfl_xor_sync(0xffffffffu, h1, m);
        float o2 = __shfl_xor_sync(0xffffffffu, h2, m);
        float a = fmaxf(h1, o1);
        float b = fminf(h1, o1);
        float c = fmaxf(fmaxf(h2, o2), b);
        h1 = a; h2 = c;
    }
    float gscore = h1 + h2;

    float gs[8];
#pragma unroll
    for (int g = 0; g < 8; g++) gs[g] = __shfl_sync(0xffffffffu, gscore, g * 4);

    unsigned gmask = 0;
    float val4 = 0.0f, val5 = 0.0f;
#pragma unroll
    for (int r = 0; r < 5; r++) {
        float best = -INFINITY; int bi = 0;
#pragma unroll
        for (int g = 0; g < 8; g++) {
            bool avail = !((gmask >> g) & 1u);
            if (avail && gs[g] > best) { best = gs[g]; bi = g; }
        }
        if (r < 4) { gmask |= 1u << bi; val4 = best; }
        else       { val5 = best; }
    }
    margin_g = val4 - val5;

    const bool inmask = (gmask >> (lane >> 2)) & 1u;
    const int ebase = lane * 8;
    float mval[8];
#pragma unroll
    for (int i = 0; i < 8; i++) mval[i] = inmask ? swb[i] : 0.0f;

    unsigned selbits = 0;
    float v8 = 0.0f, v9 = 0.0f;
#pragma unroll
    for (int r = 0; r < 9; r++) {
        float bv = -INFINITY; int bidx = 0x3fffffff;
#pragma unroll
        for (int i = 0; i < 8; i++) {
            if (!((selbits >> i) & 1u)) {
                float v = mval[i]; int e = ebase + i;
                if (v > bv || (v == bv && e < bidx)) { bv = v; bidx = e; }
            }
        }
#pragma unroll
        for (int off = 16; off >= 1; off >>= 1) {
            float ov = __shfl_xor_sync(0xffffffffu, bv, off);
            int   oi = __shfl_xor_sync(0xffffffffu, bidx, off);
            if (ov > bv || (ov == bv && oi < bidx)) { bv = ov; bidx = oi; }
        }
        if (r < 8) {
            if ((bidx >> 3) == lane) selbits |= 1u << (bidx & 7);
            if (r == 7) v8 = bv;
        } else v9 = bv;
    }
    margin_e = v8 - v9;

    float d = 0.0f;
#pragma unroll
    for (int i = 0; i < 8; i++) if ((selbits >> i) & 1u) d += score[i];
#pragma unroll
    for (int off = 16; off >= 1; off >>= 1) d += __shfl_xor_sync(0xffffffffu, d, off);
    d += 1e-20f;

    float o[8];
#pragma unroll
    for (int i = 0; i < 8; i++)
        o[i] = ((selbits >> i) & 1u) ? (score[i] / d) * 2.5f : 0.0f;

    *reinterpret_cast<float4*>(&orow[ebase])     = make_float4(o[0], o[1], o[2], o[3]);
    *reinterpret_cast<float4*>(&orow[ebase + 4]) = make_float4(o[4], o[5], o[6], o[7]);
}

// ---------------------------------------------------------------------------
// Kernel 1: fused gate GEMM (single-product fp16 mma.sync) + routing + triggers
// 128 CTAs x 256 threads. Warp tile m64 x n64. 4 k-step combos per chunk.
// ---------------------------------------------------------------------------
__global__ __launch_bounds__(NTH, 1)
void gate_fused_kernel(const float* __restrict__ A, const float* __restrict__ bias,
                       float* __restrict__ out) {
    extern __shared__ char smem[];
    const uint32_t sb = smem_u32(smem);
    const int tid  = threadIdx.x;
    const int lane = tid & 31;
    const int w    = tid >> 5;
    const int wm   = w >> 2;
    const int wn   = w & 3;
    const int m0   = blockIdx.x * M_TILE;

    float4 bv0 = *reinterpret_cast<const float4*>(bias + lane * 8);
    float4 bv1 = *reinterpret_cast<const float4*>(bias + lane * 8 + 4);

    const int arow = tid >> 1;
    const int ahalf = tid & 1;
    const float* abase_g = A + (size_t)(m0 + arow) * HIDDEN + ahalf * 32;
    const uint32_t asts_base = (uint32_t)(arow * RSTRIDE + ahalf * 64);

    // A: LDG fp32 -> fp16 -> STS (registers live only inside this call)
    auto LDSTA = [&](int it, uint32_t buf) {
        const float4* p = reinterpret_cast<const float4*>(abase_g + it * KC);
        float4 areg[8];
#pragma unroll
        for (int j = 0; j < 8; j++) areg[j] = p[j];
        const uint32_t hb = buf + OFF_A + asts_base;
#pragma unroll
        for (int j = 0; j < 8; j++) {
            float4 v = areg[j];
            sts8(hb + 8 * j,
                 packh(__float2half_rn(v.x), __float2half_rn(v.y)),
                 packh(__float2half_rn(v.z), __float2half_rn(v.w)));
        }
    };
    auto CPW = [&](int it, uint32_t buf) {
        const uint8_t* wh = g_Wh + (size_t)it * W_TILE_B;
#pragma unroll
        for (int i = 0; i < 9; i++) {                   // 9*256*16 = 36864 B
            uint32_t off = (uint32_t)(i * 256 + tid) * 16;
            CP_ASYNC16(buf + OFF_W + off, wh + off);
        }
    };

    const uint32_t a_lane = (uint32_t)((lane & 15) * RSTRIDE + (lane >> 4) * 16);
    const uint32_t b_lane = (uint32_t)(((lane & 7) + ((lane >> 4) & 1) * 8) * RSTRIDE
                                       + ((lane >> 3) & 1) * 16);
    const uint32_t am_base = (uint32_t)(wm * 64 * RSTRIDE);
    const uint32_t bn_base = (uint32_t)(wn * 64 * RSTRIDE);

    // Fragment double buffers (pipeline depth 2); combo index = k-step 0..3
    uint32_t af[2][16], bf[2][16];
    auto LDFRAG = [&](int slot, uint32_t cur, int ks) {
        const uint32_t kb = (uint32_t)ks * 32;
        const uint32_t ab = cur + OFF_A + am_base + kb + a_lane;
        const uint32_t bb = cur + OFF_W + bn_base + kb + b_lane;
#pragma unroll
        for (int mi = 0; mi < 4; mi++) ldm_x4(af[slot] + mi * 4, ab + mi * 16 * RSTRIDE);
#pragma unroll
        for (int q = 0; q < 4; q++)    ldm_x4(bf[slot] + q  * 4, bb + q  * 16 * RSTRIDE);
    };

    float acc[4][8][4];
#pragma unroll
    for (int mi = 0; mi < 4; mi++)
#pragma unroll
        for (int ni = 0; ni < 8; ni++)
#pragma unroll
            for (int q = 0; q < 4; q++) acc[mi][ni][q] = 0.0f;

    // ---- prologue
    {
        CPW(0, sb); CP_COMMIT();
        LDSTA(0, sb);
        CP_WAIT0();
        __syncthreads();
        LDFRAG(0, sb, 0);
    }

    for (int it = 0; it < NCHUNKS; it++) {
        const uint32_t cur = sb + (uint32_t)(it & 1) * STAGE_B;
        const uint32_t nxt = sb + (uint32_t)((it + 1) & 1) * STAGE_B;
        const bool more = (it + 1 < NCHUNKS);

        if (more) { CPW(it + 1, nxt); CP_COMMIT(); }

#pragma unroll
        for (int c = 0; c < 4; c++) {
            if (c < 3) LDFRAG((c + 1) & 1, cur, c + 1);
            const uint32_t* a_ = af[c & 1];
            const uint32_t* b_ = bf[c & 1];
#pragma unroll
            for (int mi = 0; mi < 4; mi++)
#pragma unroll
                for (int ni = 0; ni < 8; ni++)
                    mma16816(acc[mi][ni], a_ + mi * 4, b_ + (ni >> 1) * 4 + (ni & 1) * 2);
        }

        if (more) LDSTA(it + 1, nxt);
        CP_WAIT0();
        __syncthreads();
        if (more) LDFRAG(0, nxt, 0);
    }

    // ---- epilogue: accum frags -> smem logits (stride 264 floats)
    {
        const int gid = lane >> 2;
        const int tig = lane & 3;
#pragma unroll
        for (int mi = 0; mi < 4; mi++) {
#pragma unroll
            for (int ni = 0; ni < 8; ni++) {
                const int col = wn * 64 + ni * 8 + tig * 2;
                const int r0 = wm * 64 + mi * 16 + gid;
                uint32_t a0 = sb + (uint32_t)r0 * LSTRIDE_B + col * 4;
                sts8(a0, __float_as_uint(acc[mi][ni][0]), __float_as_uint(acc[mi][ni][1]));
                sts8(a0 + 8u * LSTRIDE_B, __float_as_uint(acc[mi][ni][2]),
                                          __float_as_uint(acc[mi][ni][3]));
            }
        }
    }
    __syncthreads();

    // ---- fused routing + margin triggers
    {
        const float bs[8] = {bv0.x, bv0.y, bv0.z, bv0.w, bv1.x, bv1.y, bv1.z, bv1.w};
        for (int i = 0; i < 16; i++) {
            const int t = w * 16 + i;
            const uint32_t src = sb + (uint32_t)t * LSTRIDE_B + lane * 32;
            float4 l0 = lds16f(src);
            float4 l1 = lds16f(src + 16);
            const float lg[8] = {l0.x, l0.y, l0.z, l0.w, l1.x, l1.y, l1.z, l1.w};
            float mg, me;
            route_token(lg, bs, out + (size_t)(m0 + t) * NUM_EXPERTS, lane, mg, me);
            if (lane == 0 && (mg < TAU_G || me < TAU_E)) {
                int p = atomicAdd(&g_fix_cnt, 1);
                if (p < NUM_TOKENS) g_fix_list[p] = m0 + t;
            }
        }
    }
}

// ---------------------------------------------------------------------------
// Kernel 2: exact fp32 repair of marginal tokens. 8 tokens per block-chunk
// (amortizes the per-chunk W read). thread = expert; f32x2 accumulation.
// ---------------------------------------------------------------------------
__global__ __launch_bounds__(256)
void repair_kernel(const float* __restrict__ A, const float* __restrict__ W,
                   const float* __restrict__ bias, float* __restrict__ out) {
    __shared__ float sA[8][1024];     // 32 KB
    __shared__ float sLog[8][264];

    const int tid  = threadIdx.x;
    const int lane = tid & 31;
    const int w    = tid >> 5;
    const int cnt  = g_fix_cnt;

    float4 bv0 = *reinterpret_cast<const float4*>(bias + lane * 8);
    float4 bv1 = *reinterpret_cast<const float4*>(bias + lane * 8 + 4);
    const float bs[8] = {bv0.x, bv0.y, bv0.z, bv0.w, bv1.x, bv1.y, bv1.z, bv1.w};

    const float* wrow = W + (size_t)tid * HIDDEN;

    for (int base = blockIdx.x * 8; base < cnt; base += gridDim.x * 8) {
        int tk[8];
#pragma unroll
        for (int i = 0; i < 8; i++) {
            int idx = base + i;
            tk[i] = g_fix_list[idx < cnt ? idx : cnt - 1];
        }

        ull acc[8][2];
#pragma unroll
        for (int t = 0; t < 8; t++) { acc[t][0] = 0ull; acc[t][1] = 0ull; }

        for (int kt = 0; kt < 7; kt++) {
            __syncthreads();
#pragma unroll
            for (int j = 0; j < 8; j++) {
                int idx = j * 256 + tid;          // 0..2047
                int t  = idx >> 8;
                int k4 = (idx & 255) * 4;
                *reinterpret_cast<float4*>(&sA[t][k4]) =
                    *reinterpret_cast<const float4*>(A + (size_t)tk[t] * HIDDEN + kt * 1024 + k4);
            }
            __syncthreads();

            const float4* wp = reinterpret_cast<const float4*>(wrow + kt * 1024);
#pragma unroll 4
            for (int k4 = 0; k4 < 256; k4++) {
                float4 wv = wp[k4];
                ull wxy = pack2(wv.x, wv.y);
                ull wzw = pack2(wv.z, wv.w);
#pragma unroll
                for (int t = 0; t < 8; t++) {
                    const ull* av = reinterpret_cast<const ull*>(&sA[t][k4 * 4]);
                    fma2(acc[t][0], av[0], wxy);
                    fma2(acc[t][1], av[1], wzw);
                }
            }
        }

#pragma unroll
        for (int t = 0; t < 8; t++) {
            float2 u0 = unpack2(acc[t][0]);
            float2 u1 = unpack2(acc[t][1]);
            sLog[t][tid] = (u0.x + u1.x) + (u0.y + u1.y);
        }
        __syncthreads();

        // 8 warps route one token each
        {
            float4 l0 = *reinterpret_cast<const float4*>(&sLog[w][lane * 8]);
            float4 l1 = *reinterpret_cast<const float4*>(&sLog[w][lane * 8 + 4]);
            const float lg[8] = {l0.x, l0.y, l0.z, l0.w, l1.x, l1.y, l1.z, l1.w};
            float mg, me;
            route_token(lg, bs, out + (size_t)tk[w] * NUM_EXPERTS, lane, mg, me);
        }
        __syncthreads();
    }
}

// ---------------------------------------------------------------------------
extern "C" void kernel_launch(void* const* d_in, const int* in_sizes, int n_in,
                              void* d_out, int out_size) {
    const float* hidden = (const float*)d_in[0];   // [16384, 7168]
    const float* weight = (const float*)d_in[1];   // [256, 7168]
    const float* bias   = (const float*)d_in[2];   // [256]
    float* out = (float*)d_out;                    // [16384, 256]

    convert_w_kernel<<<(NUM_EXPERTS * HIDDEN / 4) / 256, 256>>>(weight);

    cudaFuncSetAttribute(gate_fused_kernel,
                         cudaFuncAttributeMaxDynamicSharedMemorySize, SMEM_TOTAL);
    gate_fused_kernel<<<NUM_TOKENS / M_TILE, NTH, SMEM_TOTAL>>>(hidden, bias, out);

    repair_kernel<<<128, 256>>>(hidden, weight, bias, out);
}